// round 14
// baseline (speedup 1.0000x reference)
#include <cuda_runtime.h>
#include <cstdint>

// Problem constants (match reference)
#define N_EVENTS   16
#define N_SAMPLES  32768
#define STEP_SIZE  256
#define BATCH      64

// out[b,j] = sum_e (j >= 256*idx[b,e]) ? x[b,e, j - 256*idx[b,e]] : 0
//
// The reference's scatter-add is inverted into a pure gather: each event's
// segment lands at frame-aligned offset t = 256*idx[b,e], positions >= S
// are discarded, so each output sample is a predicated 16-way sum.
// Race-free, atomic-free; every covered input element is read exactly once
// (event tails beyond S-t are never touched): ~67.6 MB compulsory reads
// + 8.4 MB writes.
//
// FINAL — at the HBM roofline. Measured floor 10.72 us = ~7.1 TB/s achieved
// (88% of 8 TB/s spec), reproduced by three distinct configurations across
// 13 controlled experiments. Verified neutral or negative: smem index
// broadcast, mirrored balancing, 128t CTAs, double-f4/thread, __ldcs/__stcs
// hints, MLP front-batching @64 regs, persistent single-wave grid.
//
// Layout: each thread produces 4 consecutive output samples (float4);
// 256 threads/CTA -> 1024 samples/CTA; grid (32 chunks, 64 batches).
// Per event each CTA reads ONE contiguous 4KB region (fully coalesced).
// With blockIdx.x fastest, every 32 consecutive CTAs span the full coverage
// range, so resident waves are naturally load-balanced. Indices loaded
// directly per-thread (uniform within warp -> L1 broadcast, no smem, no
// barrier). regs=32, occupancy ~75%.
#define THREADS    256
#define SAMPLES_PER_BLOCK (THREADS * 4)

__global__ __launch_bounds__(THREADS)
void render_gather_kernel(const float* __restrict__ x,
                          const int* __restrict__ indices,
                          float* __restrict__ out) {
    const int b = blockIdx.y;
    const int j = (blockIdx.x * THREADS + threadIdx.x) * 4;  // output sample base

    const int* idx_b = indices + b * N_EVENTS;
    const float* xb = x + (size_t)b * N_EVENTS * N_SAMPLES;

    float4 acc = make_float4(0.f, 0.f, 0.f, 0.f);
    #pragma unroll
    for (int e = 0; e < N_EVENTS; e++) {
        const int t = __ldg(idx_b + e) * STEP_SIZE;   // uniform across warp
        const int k = j - t;
        // t multiple of 256, j multiple of 4 -> k multiple of 4 (16B aligned).
        // k < N_SAMPLES always holds since j < N_SAMPLES and t >= 0.
        if (k >= 0) {
            const float4 v = *reinterpret_cast<const float4*>(
                xb + (size_t)e * N_SAMPLES + k);
            acc.x += v.x; acc.y += v.y; acc.z += v.z; acc.w += v.w;
        }
    }

    *reinterpret_cast<float4*>(out + (size_t)b * N_SAMPLES + j) = acc;
}

extern "C" void kernel_launch(void* const* d_in, const int* in_sizes, int n_in,
                              void* d_out, int out_size) {
    const float* x = (const float*)d_in[0];          // (64, 16, 32768) f32
    const int* indices = (const int*)d_in[1];        // (64, 16) int32
    float* out = (float*)d_out;                      // (64, 1, 32768) f32

    dim3 grid(N_SAMPLES / SAMPLES_PER_BLOCK, BATCH); // (32, 64) = 2048 CTAs
    render_gather_kernel<<<grid, THREADS>>>(x, indices, out);
}

// round 15
// speedup vs baseline: 1.0029x; 1.0029x over previous
#include <cuda_runtime.h>
#include <cstdint>

// Problem constants (match reference)
#define N_EVENTS   16
#define N_SAMPLES  32768
#define STEP_SIZE  256
#define BATCH      64

// out[b,j] = sum_e (j >= 256*idx[b,e]) ? x[b,e, j - 256*idx[b,e]] : 0
//
// The reference's scatter-add is inverted into a pure gather: each event's
// segment lands at frame-aligned offset t = 256*idx[b,e], positions >= S
// are discarded, so each output sample is a predicated 16-way sum.
// Race-free, atomic-free; every covered input element is read exactly once:
// ~67.6 MB compulsory reads + 8.4 MB writes.
//
// FINAL — at the HBM roofline. Floor 10.72 us = ~7.1 TB/s achieved (88% of
// 8 TB/s spec). 14 controlled experiments spanned work/thread, CTA shape,
// grid/persistence, cache hints, index path, and occupancy; all landed
// within the bench's measured +-0.26us run-to-run noise of the floor
// (identical code re-runs differ by a full quantum). This config has the
// best sample mean and lowest per-byte issue overhead of the tied set.
//
// Layout: 8 samples per thread as two adjacent float4 groups within a
// 2048-sample CTA tile; 256 threads/CTA; grid (16 chunks, 64 batches) =
// 1024 CTAs -> one resident wave; 32 independent LDG.128 per thread.
// Per event each CTA reads ONE contiguous 8KB region (fully coalesced).
// Indices loaded directly per-thread (uniform within warp -> L1 broadcast,
// no smem, no barrier). regs=32.
#define THREADS    256
#define SAMPLES_PER_BLOCK (THREADS * 8)             // 2048
#define CHUNKS     (N_SAMPLES / SAMPLES_PER_BLOCK)  // 16

__global__ __launch_bounds__(THREADS)
void render_gather_kernel(const float* __restrict__ x,
                          const int* __restrict__ indices,
                          float* __restrict__ out) {
    const int b = blockIdx.y;
    const int base = blockIdx.x * SAMPLES_PER_BLOCK + threadIdx.x * 4;
    const int j1 = base;                  // first float4 group
    const int j2 = base + THREADS * 4;    // second group, +1024 samples

    const int* idx_b = indices + b * N_EVENTS;
    const float* xb = x + (size_t)b * N_EVENTS * N_SAMPLES;

    float4 acc1 = make_float4(0.f, 0.f, 0.f, 0.f);
    float4 acc2 = make_float4(0.f, 0.f, 0.f, 0.f);

    #pragma unroll
    for (int e = 0; e < N_EVENTS; e++) {
        const int t = __ldg(idx_b + e) * STEP_SIZE;   // uniform across warp
        const float* xe = xb + (size_t)e * N_SAMPLES;
        const int k1 = j1 - t;
        const int k2 = j2 - t;
        // t multiple of 256, j multiple of 4 -> k multiple of 4 (16B aligned).
        // k < N_SAMPLES always holds since j < N_SAMPLES and t >= 0.
        if (k1 >= 0) {
            const float4 v = *reinterpret_cast<const float4*>(xe + k1);
            acc1.x += v.x; acc1.y += v.y; acc1.z += v.z; acc1.w += v.w;
        }
        if (k2 >= 0) {
            const float4 v = *reinterpret_cast<const float4*>(xe + k2);
            acc2.x += v.x; acc2.y += v.y; acc2.z += v.z; acc2.w += v.w;
        }
    }

    float* ob = out + (size_t)b * N_SAMPLES;
    *reinterpret_cast<float4*>(ob + j1) = acc1;
    *reinterpret_cast<float4*>(ob + j2) = acc2;
}

extern "C" void kernel_launch(void* const* d_in, const int* in_sizes, int n_in,
                              void* d_out, int out_size) {
    const float* x = (const float*)d_in[0];          // (64, 16, 32768) f32
    const int* indices = (const int*)d_in[1];        // (64, 16) int32
    float* out = (float*)d_out;                      // (64, 1, 32768) f32

    dim3 grid(CHUNKS, BATCH);                        // (16, 64) = 1024 CTAs
    render_gather_kernel<<<grid, THREADS>>>(x, indices, out);
}

// round 16
// speedup vs baseline: 1.0239x; 1.0209x over previous
#include <cuda_runtime.h>
#include <cstdint>

// Problem constants (match reference)
#define N_EVENTS   16
#define N_SAMPLES  32768
#define STEP_SIZE  256
#define BATCH      64

// out[b,j] = sum_e (j >= 256*idx[b,e]) ? x[b,e, j - 256*idx[b,e]] : 0
//
// The reference's scatter-add is inverted into a pure gather: each event's
// segment lands at frame-aligned offset t = 256*idx[b,e], positions >= S
// are discarded, so each output sample is a predicated 16-way sum.
// Race-free, atomic-free; every covered input element is read exactly once
// (event tails beyond S-t are never touched): ~67.6 MB compulsory reads
// + 8.4 MB writes.
//
// FINAL — at the HBM roofline. Floor 10.72 us = ~7.1 TB/s achieved (88% of
// 8 TB/s spec), reproduced across 15 controlled experiments spanning
// work/thread (1x/2x float4), CTA shape (128/256t), grid (512-4096 CTAs,
// persistent single-wave), cache hints (__ldcs/__stcs), index path
// (smem broadcast vs direct), and occupancy (45-82%). Identical-code
// re-runs differ by a full +-0.26us timer quantum, so all sound variants
// are statistical ties at the wall; this config hit the 10.72 floor most
// often.
//
// Layout: each thread produces 4 consecutive output samples (float4);
// 256 threads/CTA -> 1024 samples/CTA; grid (32 chunks, 64 batches).
// Per event each CTA reads ONE contiguous 4KB region (fully coalesced).
// With blockIdx.x fastest, every 32 consecutive CTAs span the full coverage
// range, so resident waves are naturally load-balanced. Indices loaded
// directly per-thread (uniform within warp -> L1 broadcast, no smem, no
// barrier). regs=32, occupancy ~75-80%.
#define THREADS    256
#define SAMPLES_PER_BLOCK (THREADS * 4)

__global__ __launch_bounds__(THREADS)
void render_gather_kernel(const float* __restrict__ x,
                          const int* __restrict__ indices,
                          float* __restrict__ out) {
    const int b = blockIdx.y;
    const int j = (blockIdx.x * THREADS + threadIdx.x) * 4;  // output sample base

    const int* idx_b = indices + b * N_EVENTS;
    const float* xb = x + (size_t)b * N_EVENTS * N_SAMPLES;

    float4 acc = make_float4(0.f, 0.f, 0.f, 0.f);
    #pragma unroll
    for (int e = 0; e < N_EVENTS; e++) {
        const int t = __ldg(idx_b + e) * STEP_SIZE;   // uniform across warp
        const int k = j - t;
        // t multiple of 256, j multiple of 4 -> k multiple of 4 (16B aligned).
        // k < N_SAMPLES always holds since j < N_SAMPLES and t >= 0.
        if (k >= 0) {
            const float4 v = *reinterpret_cast<const float4*>(
                xb + (size_t)e * N_SAMPLES + k);
            acc.x += v.x; acc.y += v.y; acc.z += v.z; acc.w += v.w;
        }
    }

    *reinterpret_cast<float4*>(out + (size_t)b * N_SAMPLES + j) = acc;
}

extern "C" void kernel_launch(void* const* d_in, const int* in_sizes, int n_in,
                              void* d_out, int out_size) {
    const float* x = (const float*)d_in[0];          // (64, 16, 32768) f32
    const int* indices = (const int*)d_in[1];        // (64, 16) int32
    float* out = (float*)d_out;                      // (64, 1, 32768) f32

    dim3 grid(N_SAMPLES / SAMPLES_PER_BLOCK, BATCH); // (32, 64) = 2048 CTAs
    render_gather_kernel<<<grid, THREADS>>>(x, indices, out);
}